// round 3
// baseline (speedup 1.0000x reference)
#include <cuda_runtime.h>
#include <math.h>

#define Bb 2048
#define Mm 64
#define Dd 512
#define NROWS (Bb*Mm)     // 131072
#define NC    2560        // 5*512 stacked: [zr | zw | zf | zi | zc]
#define BK    16

// ---------------- scratch (device globals; no runtime allocation) ----------------
__device__ float g_WtBig[Dd*NC];   // stacked W1[:, :D]  transposed -> [k][c]
__device__ float g_WtX  [Dd*NC];   // stacked W1[:, D:]  transposed -> [k][c]
__device__ float g_WtFin[Dd*Dd];   // Wfin^T  [k][d]
__device__ float g_WtSub[Dd*Dd];   // Wsub^T  [k][d]
__device__ float g_bstack[NC];
__device__ float g_xterm[Bb*NC];   // x @ WtX + bstack
__device__ float g_F[NROWS*Dd];
__device__ float g_I[NROWS*Dd];
__device__ float g_C[NROWS*Dd];
__device__ float g_mem[NROWS*Dd];
__device__ float g_sRp[NROWS*8];   // partial h_r . W2r per 64-col chunk
__device__ float g_sWp[NROWS*8];
__device__ float g_simr[NROWS];
__device__ float g_simw[NROWS];
__device__ float g_subvec[Bb*Dd];

// ---------------- weight transpose / stacking ----------------
__global__ void prep_k(const float* __restrict__ W1r, const float* __restrict__ W1w,
                       const float* __restrict__ Wf,  const float* __restrict__ Wi,
                       const float* __restrict__ Wc,
                       const float* __restrict__ b1r, const float* __restrict__ b1w,
                       const float* __restrict__ bf,  const float* __restrict__ bi,
                       const float* __restrict__ bc,
                       const float* __restrict__ Wfin, const float* __restrict__ Wsub)
{
    int idx = blockIdx.x*blockDim.x + threadIdx.x;
    int stride = gridDim.x*blockDim.x;
    for (int i = idx; i < Dd*NC; i += stride) {
        int k = i / NC, c = i % NC;
        int j = c >> 9, d = c & 511;
        const float* W = (j==0)?W1r:(j==1)?W1w:(j==2)?Wf:(j==3)?Wi:Wc;
        g_WtBig[i] = W[d*(2*Dd) + k];
        g_WtX[i]   = W[d*(2*Dd) + Dd + k];
        if (i < Dd*Dd) {
            int kk = i >> 9, dd = i & 511;
            g_WtFin[i] = Wfin[dd*Dd + kk];
            g_WtSub[i] = Wsub[dd*Dd + kk];
        }
        if (i < NC) {
            const float* bb = (j==0)?b1r:(j==1)?b1w:(j==2)?bf:(j==3)?bi:bc;
            g_bstack[i] = bb[d];
        }
    }
}

// ---------------- fused tiled GEMM (BM=64, BN=64, BK=16, 4x4 micro-tile) ----------
// epi: 0 = xterm (out=g_xterm, +bstack)
//      1 = main  (A=sub_memory; per-j activations; F/I/C + s partials)
//      2 = fin   (A=g_subvec, W=WtFin, tanh, -> out[b,0,:])
//      3 = sub   (A=g_mem,   W=WtSub, tanh, -> out[b,1+m,:])
__global__ void __launch_bounds__(256)
gemm_k(int epi, const float* __restrict__ Ain,
       const float* __restrict__ bias,
       const float* __restrict__ w2r, const float* __restrict__ w2w,
       float* __restrict__ out)
{
    __shared__ float As[BK][68];
    __shared__ float Ws[BK][68];
    __shared__ float w2s[64];
    __shared__ float red[64][17];

    const int tid = threadIdx.x;
    const int tm = tid & 15;      // m-group 0..15
    const int td = tid >> 4;      // n-group 0..15
    const int chunk  = blockIdx.x;
    const int rowblk = blockIdx.y;
    const int row0 = rowblk * 64;
    const int n0   = chunk * 64;

    const float* A;
    const float* W;
    int ldw;
    if (epi == 0)      { A = Ain;      W = g_WtX;   ldw = NC; }
    else if (epi == 1) { A = Ain;      W = g_WtBig; ldw = NC; }
    else if (epi == 2) { A = g_subvec; W = g_WtFin; ldw = Dd; }
    else               { A = g_mem;    W = g_WtSub; ldw = Dd; }

    int jmat = 0;
    if (epi == 1) {
        jmat = chunk >> 3;
        if (jmat == 0 && tid < 64) w2s[tid] = w2r[(chunk & 7)*64 + tid];
        if (jmat == 1 && tid < 64) w2s[tid] = w2w[(chunk & 7)*64 + tid];
    }

    const int ar = tid >> 2;        // 0..63
    const int ak = (tid & 3) * 4;   // 0,4,8,12
    const int wk = tid >> 4;        // 0..15
    const int wn = (tid & 15) * 4;  // 0..60

    float acc[4][4];
#pragma unroll
    for (int i=0;i<4;i++)
#pragma unroll
        for (int jj=0;jj<4;jj++) acc[i][jj]=0.f;

    for (int k0 = 0; k0 < Dd; k0 += BK) {
        __syncthreads();
        float4 av = *(const float4*)&A[(row0+ar)*Dd + k0 + ak];
        As[ak+0][ar]=av.x; As[ak+1][ar]=av.y; As[ak+2][ar]=av.z; As[ak+3][ar]=av.w;
        float4 wv = *(const float4*)&W[(k0+wk)*ldw + n0 + wn];
        *(float4*)&Ws[wk][wn] = wv;
        __syncthreads();
#pragma unroll
        for (int k=0;k<BK;k++){
            float4 a = *(const float4*)&As[k][tm*4];
            float4 b = *(const float4*)&Ws[k][td*4];
            acc[0][0] += a.x*b.x; acc[0][1] += a.x*b.y; acc[0][2] += a.x*b.z; acc[0][3] += a.x*b.w;
            acc[1][0] += a.y*b.x; acc[1][1] += a.y*b.y; acc[1][2] += a.y*b.z; acc[1][3] += a.y*b.w;
            acc[2][0] += a.z*b.x; acc[2][1] += a.z*b.y; acc[2][2] += a.z*b.z; acc[2][3] += a.z*b.w;
            acc[3][0] += a.w*b.x; acc[3][1] += a.w*b.y; acc[3][2] += a.w*b.z; acc[3][3] += a.w*b.w;
        }
    }

    if (epi == 0) {
        // xterm = x @ WtX + bstack  (bias from global stack)
#pragma unroll
        for (int i=0;i<4;i++){
            int r = row0 + tm*4 + i;
#pragma unroll
            for (int jj=0;jj<4;jj++){
                int c = n0 + td*4 + jj;
                g_xterm[r*NC + c] = acc[i][jj] + g_bstack[c];
            }
        }
    } else if (epi == 1) {
        int b = rowblk;
        int ch8 = chunk & 7;
        if (jmat <= 1) {
            // h = relu(z); partial dot with W2 over this 64-col d-range
            float pr[4] = {0.f,0.f,0.f,0.f};
#pragma unroll
            for (int i=0;i<4;i++){
#pragma unroll
                for (int jj=0;jj<4;jj++){
                    int c = n0 + td*4 + jj;
                    float z = acc[i][jj] + g_xterm[b*NC + c];
                    float h = fmaxf(z, 0.f);
                    pr[i] += h * w2s[td*4 + jj];
                }
            }
            __syncthreads();
#pragma unroll
            for (int i=0;i<4;i++) red[tm*4+i][td] = pr[i];
            __syncthreads();
            if (tid < 64) {
                float s = 0.f;
#pragma unroll
                for (int t=0;t<16;t++) s += red[tid][t];
                float* dst = (jmat==0) ? g_sRp : g_sWp;
                dst[(b*64 + tid)*8 + ch8] = s;
            }
        } else {
            float* dst = (jmat==2) ? g_F : (jmat==3) ? g_I : g_C;
#pragma unroll
            for (int i=0;i<4;i++){
                int m = tm*4 + i;
                int d0 = ch8*64 + td*4;
                float zv[4];
#pragma unroll
                for (int jj=0;jj<4;jj++)
                    zv[jj] = acc[i][jj] + g_xterm[b*NC + n0 + td*4 + jj];
                float4 v;
                if (jmat == 4) {
                    v.x = tanhf(zv[0]); v.y = tanhf(zv[1]); v.z = tanhf(zv[2]); v.w = tanhf(zv[3]);
                } else {
                    v.x = 1.f/(1.f+expf(-zv[0])); v.y = 1.f/(1.f+expf(-zv[1]));
                    v.z = 1.f/(1.f+expf(-zv[2])); v.w = 1.f/(1.f+expf(-zv[3]));
                }
                *(float4*)&dst[(b*64 + m)*Dd + d0] = v;
            }
        }
    } else {
        // epi 2: read_vec row -> out[b,0,:]; epi 3: new_mem -> out[b,1+m,:]
#pragma unroll
        for (int i=0;i<4;i++){
            int r = row0 + tm*4 + i;
            int c0 = n0 + td*4;
            int outbase;
            if (epi == 2) outbase = r * (65*512);
            else          outbase = (r + (r >> 6) + 1) * 512;
            float4 v;
            v.x = tanhf(acc[i][0] + bias[c0+0]);
            v.y = tanhf(acc[i][1] + bias[c0+1]);
            v.z = tanhf(acc[i][2] + bias[c0+2]);
            v.w = tanhf(acc[i][3] + bias[c0+3]);
            *(float4*)&out[outbase + c0] = v;
        }
    }
}

// ---------------- softmax over M=64 (deterministic, block per batch) -------------
__global__ void softmax_k() {
    int b = blockIdx.x, m = threadIdx.x;
    float sr = 0.f, sw = 0.f;
    const float* pr = &g_sRp[(b*64+m)*8];
    const float* pw = &g_sWp[(b*64+m)*8];
#pragma unroll
    for (int p=0;p<8;p++){ sr += pr[p]; sw += pw[p]; }

    __shared__ float sh[64];
    // r-softmax
    sh[m] = sr; __syncthreads();
    for (int s=32;s>0;s>>=1){ if(m<s) sh[m]=fmaxf(sh[m],sh[m+s]); __syncthreads(); }
    float mxr = sh[0]; __syncthreads();
    float er = expf(sr - mxr);
    sh[m] = er; __syncthreads();
    for (int s=32;s>0;s>>=1){ if(m<s) sh[m]+=sh[m+s]; __syncthreads(); }
    float sumr = sh[0]; __syncthreads();
    g_simr[b*64+m] = er / sumr;
    // w-softmax
    sh[m] = sw; __syncthreads();
    for (int s=32;s>0;s>>=1){ if(m<s) sh[m]=fmaxf(sh[m],sh[m+s]); __syncthreads(); }
    float mxw = sh[0]; __syncthreads();
    float ew = expf(sw - mxw);
    sh[m] = ew; __syncthreads();
    for (int s=32;s>0;s>>=1){ if(m<s) sh[m]+=sh[m+s]; __syncthreads(); }
    float sumw = sh[0]; __syncthreads();
    g_simw[b*64+m] = ew / sumw;
}

// ---------------- sub_vec = sum_m sub_memory * sim_r -----------------------------
__global__ void subvec_k(const float* __restrict__ sub) {
    int b = blockIdx.x, d = threadIdx.x;      // 512 threads
    __shared__ float ss[64];
    if (d < 64) ss[d] = g_simr[b*64 + d];
    __syncthreads();
    const float* base = sub + (size_t)b*64*512 + d;
    float acc = 0.f;
#pragma unroll
    for (int m=0;m<64;m++) acc += base[m*512] * ss[m];
    g_subvec[b*512 + d] = acc;
}

// ---------------- mem = (1 - sw*f)*sub + i*c*sw ----------------------------------
__global__ void mem_k(const float* __restrict__ sub) {
    int i4 = blockIdx.x*blockDim.x + threadIdx.x;   // float4 index
    const int n4 = NROWS*Dd/4;                      // 16,777,216
    if (i4 >= n4) return;
    int r = i4 >> 7;                                // (i4*4)/512
    float sw = g_simw[r];
    float4 s  = ((const float4*)sub)[i4];
    float4 f  = ((const float4*)g_F)[i4];
    float4 ii = ((const float4*)g_I)[i4];
    float4 c  = ((const float4*)g_C)[i4];
    float4 o;
    o.x = (1.f - sw*f.x)*s.x + ii.x*c.x*sw;
    o.y = (1.f - sw*f.y)*s.y + ii.y*c.y*sw;
    o.z = (1.f - sw*f.z)*s.z + ii.z*c.z*sw;
    o.w = (1.f - sw*f.w)*s.w + ii.w*c.w*sw;
    ((float4*)g_mem)[i4] = o;
}

// ---------------- launch ----------------------------------------------------------
extern "C" void kernel_launch(void* const* d_in, const int* in_sizes, int n_in,
                              void* d_out, int out_size)
{
    const float* x    = (const float*)d_in[0];
    const float* sub  = (const float*)d_in[1];
    const float* W1r  = (const float*)d_in[2];
    const float* b1r  = (const float*)d_in[3];
    const float* W2r  = (const float*)d_in[4];
    /* b2r = d_in[5]  -- softmax-invariant, unused */
    const float* W1w  = (const float*)d_in[6];
    const float* b1w  = (const float*)d_in[7];
    const float* W2w  = (const float*)d_in[8];
    /* b2w = d_in[9]  -- unused */
    const float* Wf   = (const float*)d_in[10];
    const float* bf   = (const float*)d_in[11];
    const float* Wi   = (const float*)d_in[12];
    const float* bi   = (const float*)d_in[13];
    const float* Wc   = (const float*)d_in[14];
    const float* bc   = (const float*)d_in[15];
    const float* Wsub = (const float*)d_in[16];
    const float* bsub = (const float*)d_in[17];
    const float* Wfin = (const float*)d_in[18];
    const float* bfin = (const float*)d_in[19];
    float* out = (float*)d_out;

    // 1. transpose/stack weights + bias stack
    prep_k<<<2048, 256>>>(W1r, W1w, Wf, Wi, Wc, b1r, b1w, bf, bi, bc, Wfin, Wsub);

    // 2. xterm = x @ WtX + bstack   [2048 x 2560]
    gemm_k<<<dim3(40, 32), 256>>>(0, x, nullptr, nullptr, nullptr, nullptr);

    // 3. main fused GEMM: sub_memory @ WtBig + xterm -> s partials, F, I, C
    gemm_k<<<dim3(40, 2048), 256>>>(1, sub, nullptr, W2r, W2w, nullptr);

    // 4. softmax over slots
    softmax_k<<<2048, 64>>>();

    // 5. read attention pooling
    subvec_k<<<2048, 512>>>(sub);

    // 6. gated memory update (elementwise)
    mem_k<<<(NROWS*Dd/4 + 255)/256, 256>>>(sub);

    // 7. read_vec = tanh(sub_vec @ Wfin^T + bfin) -> out[b,0,:]
    gemm_k<<<dim3(8, 32), 256>>>(2, nullptr, bfin, nullptr, nullptr, out);

    // 8. new_mem = tanh(mem @ Wsub^T + bsub) -> out[b,1+m,:]
    gemm_k<<<dim3(8, 2048), 256>>>(3, nullptr, bsub, nullptr, nullptr, out);
}

// round 5
// speedup vs baseline: 2.9825x; 2.9825x over previous
#include <cuda_runtime.h>
#include <math.h>
#include <stdint.h>

#define Bb 2048
#define Mm 64
#define Dd 512
#define NROWS (Bb*Mm)     // 131072
#define NC    2560        // 5*512 stacked cols: [zr | zw | zf | zi | zc]
#define BM    128
#define BN    128
#define BK    32
#define NKCH  (Dd/BK)     // 16
#define SMEM_BYTES (4*128*36*4)   // 2 bufs x (A + B) x 18432B = 73728

// ---------------- scratch (device globals; no runtime allocation) ----------------
__device__ float g_Wbig [NC*Dd];   // stacked W1[:, :D]  rows=c(out), k contiguous (B op)
__device__ float g_WbigX[NC*Dd];   // stacked W1[:, D:]
__device__ float g_bstack[NC];
__device__ float g_xterm[Bb*NC];   // x @ WX^T + bstack
__device__ float g_F[(size_t)NROWS*Dd];
__device__ float g_I[(size_t)NROWS*Dd];
__device__ float g_C[(size_t)NROWS*Dd];
__device__ float g_mem[(size_t)NROWS*Dd];
__device__ float g_sRp[NROWS*8];   // 8 score partials per row (4 nblocks x 2 warp_n)
__device__ float g_sWp[NROWS*8];
__device__ float g_simr[NROWS];
__device__ float g_simw[NROWS];
__device__ float g_subvec[Bb*Dd];

__device__ __forceinline__ uint32_t smem_u32(const void* p){
    uint32_t a;
    asm("{ .reg .u64 t; cvta.to.shared.u64 t, %1; cvt.u32.u64 %0, t; }" : "=r"(a) : "l"(p));
    return a;
}
__device__ __forceinline__ float fsig(float z){ return __fdividef(1.f, 1.f + __expf(-z)); }
__device__ __forceinline__ float ftanh(float z){ return __fdividef(2.f, 1.f + __expf(-2.f*z)) - 1.f; }

// ---------------- weight stacking (pure copy; rows already K-major) ---------------
__global__ void prep_k(const float* __restrict__ W1r, const float* __restrict__ W1w,
                       const float* __restrict__ Wf,  const float* __restrict__ Wi,
                       const float* __restrict__ Wc,
                       const float* __restrict__ b1r, const float* __restrict__ b1w,
                       const float* __restrict__ bf,  const float* __restrict__ bi,
                       const float* __restrict__ bc)
{
    int i = blockIdx.x*blockDim.x + threadIdx.x;
    if (i < NC*Dd) {
        int c = i >> 9, k = i & 511;
        int j = c >> 9, d = c & 511;
        const float* W = (j==0)?W1r:(j==1)?W1w:(j==2)?Wf:(j==3)?Wi:Wc;
        g_Wbig[i]  = W[d*(2*Dd) + k];
        g_WbigX[i] = W[d*(2*Dd) + Dd + k];
        if (i < NC) {
            const float* bb = (j==0)?b1r:(j==1)?b1w:(j==2)?bf:(j==3)?bi:bc;
            g_bstack[i] = bb[d];
        }
    }
}

// ---------------- tf32 mma.sync GEMM + fused epilogues -----------------------------
// epi 0: xterm  (A=x,       B=g_WbigX, +bstack       -> g_xterm)
// epi 1: main   (A=sub_mem, B=g_Wbig,  +xterm        -> score partials / F / I / C)
// epi 2: fin    (A=g_subvec,B=Wfin,    +bfin, tanh   -> out[b,0,:])
// epi 3: sub    (A=g_mem,   B=Wsub,    +bsub, tanh   -> out[b,1+m,:])
__global__ void __launch_bounds__(256,1)
gemm_t(int epi, const float* __restrict__ Aext, const float* __restrict__ Bext,
       const float* __restrict__ biasExt,
       const float* __restrict__ w2r, const float* __restrict__ w2w,
       float* __restrict__ out)
{
    extern __shared__ float sm[];
    const uint32_t s0 = smem_u32(sm);

    const int tid  = threadIdx.x;
    const int lane = tid & 31, wid = tid >> 5;
    const int wm = wid & 3, wn = wid >> 2;      // 4x2 warp grid
    const int qrow = lane >> 2;                 // 0..7
    const int qcol = (lane & 3) * 2;
    const int row0 = blockIdx.y * BM;
    const int n0   = blockIdx.x * BN;

    const float* A  = (epi==2) ? g_subvec : (epi==3) ? g_mem : Aext;
    const float* Bw = (epi==0) ? g_WbigX  : (epi==1) ? g_Wbig : Bext;
    const float* bias = (epi==0) ? g_bstack : biasExt;

    const float* Arow = A  + (size_t)row0 * Dd;
    const float* Brow = Bw + (size_t)n0   * Dd;

    float acc[2][8][4];
#pragma unroll
    for (int mt=0;mt<2;mt++)
#pragma unroll
        for (int nt=0;nt<8;nt++)
#pragma unroll
            for (int q=0;q<4;q++) acc[mt][nt][q]=0.f;

    // async chunk loader: A/B tiles 128 rows x 32 k-floats, smem stride 36
#define LOADC(kc, buf) do {                                                   \
    int k0 = (kc)*BK;                                                         \
    _Pragma("unroll")                                                         \
    for (int j=0;j<4;j++){                                                    \
        int idx = j*256 + tid;                                                \
        int r = idx >> 3, c = idx & 7;                                        \
        const float* ga = Arow + (size_t)r*Dd + k0 + c*4;                     \
        const float* gb = Brow + (size_t)r*Dd + k0 + c*4;                     \
        uint32_t sa = s0 + (uint32_t)(((buf)*4608 + r*36 + c*4)*4);           \
        uint32_t sb = s0 + (uint32_t)((9216 + (buf)*4608 + r*36 + c*4)*4);    \
        asm volatile("cp.async.cg.shared.global [%0],[%1],16;" :: "r"(sa), "l"(ga)); \
        asm volatile("cp.async.cg.shared.global [%0],[%1],16;" :: "r"(sb), "l"(gb)); \
    }                                                                         \
    asm volatile("cp.async.commit_group;" ::: "memory");                      \
} while(0)

    LOADC(0, 0);

    for (int i = 0; i < NKCH; i++) {
        int buf = i & 1;
        if (i + 1 < NKCH) {
            LOADC(i + 1, buf ^ 1);
            asm volatile("cp.async.wait_group 1;" ::: "memory");
        } else {
            asm volatile("cp.async.wait_group 0;" ::: "memory");
        }
        __syncthreads();

        const float* Ab = sm + buf*4608;
        const float* Bs = sm + 9216 + buf*4608;
        const int am0 = wm*32 + qrow;
        const int bn0 = wn*64 + qrow;
#pragma unroll
        for (int s = 0; s < 4; s++) {
            int kk = s*8 + (lane & 3);
            uint32_t a[2][4];
#pragma unroll
            for (int mt=0;mt<2;mt++){
                a[mt][0] = __float_as_uint(Ab[(am0+mt*16  )*36 + kk  ]);
                a[mt][1] = __float_as_uint(Ab[(am0+mt*16+8)*36 + kk  ]);
                a[mt][2] = __float_as_uint(Ab[(am0+mt*16  )*36 + kk+4]);
                a[mt][3] = __float_as_uint(Ab[(am0+mt*16+8)*36 + kk+4]);
            }
            uint32_t b[8][2];
#pragma unroll
            for (int nt=0;nt<8;nt++){
                b[nt][0] = __float_as_uint(Bs[(bn0+nt*8)*36 + kk  ]);
                b[nt][1] = __float_as_uint(Bs[(bn0+nt*8)*36 + kk+4]);
            }
#pragma unroll
            for (int mt=0;mt<2;mt++)
#pragma unroll
                for (int nt=0;nt<8;nt++){
                    asm volatile(
                        "mma.sync.aligned.m16n8k8.row.col.f32.tf32.tf32.f32 "
                        "{%0,%1,%2,%3}, {%4,%5,%6,%7}, {%8,%9}, {%0,%1,%2,%3};"
                        : "+f"(acc[mt][nt][0]), "+f"(acc[mt][nt][1]),
                          "+f"(acc[mt][nt][2]), "+f"(acc[mt][nt][3])
                        : "r"(a[mt][0]), "r"(a[mt][1]), "r"(a[mt][2]), "r"(a[mt][3]),
                          "r"(b[nt][0]), "r"(b[nt][1]));
                }
        }
        __syncthreads();
    }
#undef LOADC

    // ---------------- epilogue -----------------------------------------------------
    const int jt = n0 >> 9;                 // epi1: 0=r 1=w 2=F 3=I 4=C

    if (epi == 1 && jt < 2) {
        const float* w2 = (jt == 0) ? w2r : w2w;
        float* dstp = (jt == 0) ? g_sRp : g_sWp;
        int nblk2 = ((n0 & 511) >> 7) * 2 + wn;       // 0..7
#pragma unroll
        for (int mt=0;mt<2;mt++){
            float sp0 = 0.f, sp1 = 0.f;               // row halves qrow / qrow+8
#pragma unroll
            for (int nt=0;nt<8;nt++){
                int col = ((n0 + wn*64 + nt*8 + qcol) & 511);
                float w0 = __ldg(w2 + col), w1 = __ldg(w2 + col + 1);
                sp0 += fmaxf(acc[mt][nt][0],0.f)*w0 + fmaxf(acc[mt][nt][1],0.f)*w1;
                sp1 += fmaxf(acc[mt][nt][2],0.f)*w0 + fmaxf(acc[mt][nt][3],0.f)*w1;
            }
            // NOTE: scores need +xterm too
            int r0g = row0 + wm*32 + mt*16 + qrow;
            // add xterm contribution: z = acc + xterm; relu(z)*w2 — must add before relu!
            // redo with xterm folded in:
            sp0 = 0.f; sp1 = 0.f;
            const float* xt0 = g_xterm + (size_t)(r0g >> 6) * NC;
            const float* xt1 = g_xterm + (size_t)((r0g + 8) >> 6) * NC;
#pragma unroll
            for (int nt=0;nt<8;nt++){
                int cg = n0 + wn*64 + nt*8 + qcol;
                int col = cg & 511;
                float w0 = __ldg(w2 + col), w1 = __ldg(w2 + col + 1);
                float x00 = __ldg(xt0 + cg), x01 = __ldg(xt0 + cg + 1);
                float x10 = __ldg(xt1 + cg), x11 = __ldg(xt1 + cg + 1);
                sp0 += fmaxf(acc[mt][nt][0]+x00,0.f)*w0 + fmaxf(acc[mt][nt][1]+x01,0.f)*w1;
                sp1 += fmaxf(acc[mt][nt][2]+x10,0.f)*w0 + fmaxf(acc[mt][nt][3]+x11,0.f)*w1;
            }
            sp0 += __shfl_xor_sync(0xffffffffu, sp0, 1);
            sp0 += __shfl_xor_sync(0xffffffffu, sp0, 2);
            sp1 += __shfl_xor_sync(0xffffffffu, sp1, 1);
            sp1 += __shfl_xor_sync(0xffffffffu, sp1, 2);
            if ((lane & 3) == 0) {
                dstp[(size_t)r0g*8 + nblk2]       = sp0;
                dstp[(size_t)(r0g+8)*8 + nblk2]   = sp1;
            }
        }
        return;
    }

#pragma unroll
    for (int mt=0;mt<2;mt++){
        int r0g = row0 + wm*32 + mt*16 + qrow;
#pragma unroll
        for (int h=0;h<2;h++){
            int row = r0g + h*8;
#pragma unroll
            for (int nt=0;nt<8;nt++){
                int cg = n0 + wn*64 + nt*8 + qcol;
                float c0 = acc[mt][nt][h*2+0];
                float c1 = acc[mt][nt][h*2+1];
                if (epi == 0) {
                    float2 o = { c0 + bias[cg], c1 + bias[cg+1] };
                    *(float2*)(g_xterm + (size_t)row*NC + cg) = o;
                } else if (epi == 1) {
                    const float* xt = g_xterm + (size_t)(row >> 6) * NC;
                    float z0 = c0 + __ldg(xt + cg);
                    float z1 = c1 + __ldg(xt + cg + 1);
                    float* dst = ((jt==2)?g_F:(jt==3)?g_I:g_C) + (size_t)row*Dd + (cg & 511);
                    float2 o;
                    if (jt == 4) { o.x = ftanh(z0); o.y = ftanh(z1); }
                    else         { o.x = fsig(z0);  o.y = fsig(z1);  }
                    *(float2*)dst = o;
                } else {
                    size_t ob = (epi == 2) ? (size_t)row * (65*Dd)
                                           : ((size_t)(row >> 6) * 65 + 1 + (row & 63)) * Dd;
                    float2 o = { ftanh(c0 + bias[cg]), ftanh(c1 + bias[cg+1]) };
                    *(float2*)(out + ob + cg) = o;
                }
            }
        }
    }
}

// ---------------- softmax over M=64 ------------------------------------------------
__global__ void softmax_k() {
    int b = blockIdx.x, m = threadIdx.x;
    int row = b*64 + m;
    float sr = 0.f, sw = 0.f;
#pragma unroll
    for (int p=0;p<8;p++){ sr += g_sRp[(size_t)row*8+p]; sw += g_sWp[(size_t)row*8+p]; }

    __shared__ float sh[64];
    sh[m] = sr; __syncthreads();
    for (int s=32;s>0;s>>=1){ if(m<s) sh[m]=fmaxf(sh[m],sh[m+s]); __syncthreads(); }
    float mxr = sh[0]; __syncthreads();
    float er = expf(sr - mxr);
    sh[m] = er; __syncthreads();
    for (int s=32;s>0;s>>=1){ if(m<s) sh[m]+=sh[m+s]; __syncthreads(); }
    float sumr = sh[0]; __syncthreads();
    g_simr[row] = er / sumr;

    sh[m] = sw; __syncthreads();
    for (int s=32;s>0;s>>=1){ if(m<s) sh[m]=fmaxf(sh[m],sh[m+s]); __syncthreads(); }
    float mxw = sh[0]; __syncthreads();
    float ew = expf(sw - mxw);
    sh[m] = ew; __syncthreads();
    for (int s=32;s>0;s>>=1){ if(m<s) sh[m]+=sh[m+s]; __syncthreads(); }
    float sumw = sh[0]; __syncthreads();
    g_simw[row] = ew / sumw;
}

// ---------------- sub_vec = sum_m sub_memory * sim_r --------------------------------
__global__ void subvec_k(const float* __restrict__ sub) {
    int b = blockIdx.x, d = threadIdx.x;
    __shared__ float ss[64];
    if (d < 64) ss[d] = g_simr[b*64 + d];
    __syncthreads();
    const float* base = sub + (size_t)b*64*512 + d;
    float acc = 0.f;
#pragma unroll
    for (int m=0;m<64;m++) acc += base[m*512] * ss[m];
    g_subvec[b*512 + d] = acc;
}

// ---------------- mem = (1 - sw*f)*sub + i*c*sw --------------------------------------
__global__ void mem_k(const float* __restrict__ sub) {
    int i4 = blockIdx.x*blockDim.x + threadIdx.x;
    const int n4 = NROWS*(Dd/4);
    if (i4 >= n4) return;
    int r = i4 >> 7;
    float sw = g_simw[r];
    float4 s  = ((const float4*)sub)[i4];
    float4 f  = ((const float4*)g_F)[i4];
    float4 ii = ((const float4*)g_I)[i4];
    float4 c  = ((const float4*)g_C)[i4];
    float4 o;
    o.x = (1.f - sw*f.x)*s.x + ii.x*c.x*sw;
    o.y = (1.f - sw*f.y)*s.y + ii.y*c.y*sw;
    o.z = (1.f - sw*f.z)*s.z + ii.z*c.z*sw;
    o.w = (1.f - sw*f.w)*s.w + ii.w*c.w*sw;
    ((float4*)g_mem)[i4] = o;
}

// ---------------- launch --------------------------------------------------------------
extern "C" void kernel_launch(void* const* d_in, const int* in_sizes, int n_in,
                              void* d_out, int out_size)
{
    const float* x    = (const float*)d_in[0];
    const float* sub  = (const float*)d_in[1];
    const float* W1r  = (const float*)d_in[2];
    const float* b1r  = (const float*)d_in[3];
    const float* W2r  = (const float*)d_in[4];
    const float* W1w  = (const float*)d_in[6];
    const float* b1w  = (const float*)d_in[7];
    const float* W2w  = (const float*)d_in[8];
    const float* Wf   = (const float*)d_in[10];
    const float* bf   = (const float*)d_in[11];
    const float* Wi   = (const float*)d_in[12];
    const float* bi   = (const float*)d_in[13];
    const float* Wc   = (const float*)d_in[14];
    const float* bc   = (const float*)d_in[15];
    const float* Wsub = (const float*)d_in[16];
    const float* bsub = (const float*)d_in[17];
    const float* Wfin = (const float*)d_in[18];
    const float* bfin = (const float*)d_in[19];
    float* out = (float*)d_out;

    cudaFuncSetAttribute(gemm_t, cudaFuncAttributeMaxDynamicSharedMemorySize, SMEM_BYTES);

    // 1. stack weights/biases
    prep_k<<<(NC*Dd + 255)/256, 256>>>(W1r, W1w, Wf, Wi, Wc, b1r, b1w, bf, bi, bc);

    // 2. xterm = x @ WX^T + bstack    [2048 x 2560]
    gemm_t<<<dim3(NC/BN, Bb/BM), 256, SMEM_BYTES>>>(0, x, nullptr, nullptr, nullptr, nullptr, nullptr);

    // 3. main: sub_memory @ Wbig^T + xterm -> score partials, F, I, C
    gemm_t<<<dim3(NC/BN, NROWS/BM), 256, SMEM_BYTES>>>(1, sub, nullptr, nullptr, W2r, W2w, nullptr);

    // 4. softmax over slots
    softmax_k<<<Bb, 64>>>();

    // 5. read attention pooling
    subvec_k<<<Bb, 512>>>(sub);

    // 6. gated memory update
    mem_k<<<(NROWS*(Dd/4) + 255)/256, 256>>>(sub);

    // 7. read_vec = tanh(sub_vec @ Wfin^T + bfin) -> out[b,0,:]
    gemm_t<<<dim3(Dd/BN, Bb/BM), 256, SMEM_BYTES>>>(2, nullptr, Wfin, bfin, nullptr, nullptr, out);

    // 8. new_mem = tanh(mem @ Wsub^T + bsub) -> out[b,1+m,:]
    gemm_t<<<dim3(Dd/BN, NROWS/BM), 256, SMEM_BYTES>>>(3, nullptr, Wsub, bsub, nullptr, nullptr, out);
}

// round 6
// speedup vs baseline: 3.3592x; 1.1263x over previous
#include <cuda_runtime.h>
#include <math.h>
#include <stdint.h>

#define Bb 2048
#define Mm 64
#define Dd 512
#define NROWS (Bb*Mm)     // 131072
#define NC    2560        // stacked cols: [zr | zw | zF | interleaved(zI,zC)]
#define BM    128
#define BN    128
#define BK    32
#define NKCH  (Dd/BK)     // 16
#define STG   4
#define SFLT  4608        // floats per tile buffer (128*36)
#define SMEM_BYTES (STG*2*SFLT*4)   // 147456

// ---------------- scratch (device globals) -----------------------------------------
__device__ float g_Wbig [NC*Dd];
__device__ float g_WbigX[NC*Dd];
__device__ float g_bstack[NC];
__device__ float g_xterm[Bb*NC];
__device__ float g_F[(size_t)NROWS*Dd];
__device__ float g_P[(size_t)NROWS*Dd];   // sigmoid(zI)*tanh(zC)
__device__ float g_mem[(size_t)NROWS*Dd];
__device__ float g_sRp[NROWS*8];
__device__ float g_sWp[NROWS*8];
__device__ float g_simr[NROWS];
__device__ float g_simw[NROWS];
__device__ float g_subvec[Bb*Dd];

__device__ __forceinline__ uint32_t smem_u32(const void* p){
    uint32_t a;
    asm("{ .reg .u64 t; cvta.to.shared.u64 t, %1; cvt.u32.u64 %0, t; }" : "=r"(a) : "l"(p));
    return a;
}
__device__ __forceinline__ float fsig(float z){ return __fdividef(1.f, 1.f + __expf(-z)); }
__device__ __forceinline__ float ftanh(float z){ return __fdividef(2.f, 1.f + __expf(-2.f*z)) - 1.f; }
__device__ __forceinline__ void ldmx4(uint32_t* r, uint32_t addr){
    asm volatile("ldmatrix.sync.aligned.m8n8.x4.shared.b16 {%0,%1,%2,%3}, [%4];"
        : "=r"(r[0]), "=r"(r[1]), "=r"(r[2]), "=r"(r[3]) : "r"(addr));
}
__device__ __forceinline__ void mma8(float* d, const uint32_t* a, const uint32_t* b){
    asm volatile(
        "mma.sync.aligned.m16n8k8.row.col.f32.tf32.tf32.f32 "
        "{%0,%1,%2,%3}, {%4,%5,%6,%7}, {%8,%9}, {%0,%1,%2,%3};"
        : "+f"(d[0]), "+f"(d[1]), "+f"(d[2]), "+f"(d[3])
        : "r"(a[0]), "r"(a[1]), "r"(a[2]), "r"(a[3]), "r"(b[0]), "r"(b[1]));
}

// ---------------- weight stacking: [Wr | Ww | WF | interleave(WI,WC)] ---------------
__global__ void prep_k(const float* __restrict__ W1r, const float* __restrict__ W1w,
                       const float* __restrict__ Wf,  const float* __restrict__ Wi,
                       const float* __restrict__ Wc,
                       const float* __restrict__ b1r, const float* __restrict__ b1w,
                       const float* __restrict__ bf,  const float* __restrict__ bi,
                       const float* __restrict__ bc)
{
    int i = blockIdx.x*blockDim.x + threadIdx.x;
    if (i < NC*Dd) {
        int c = i >> 9, k = i & 511;
        const float* W; int d;
        if (c < 1536) { int j = c >> 9; d = c & 511; W = (j==0)?W1r:(j==1)?W1w:Wf; }
        else          { int t = c - 1536; d = t >> 1; W = (t&1)?Wc:Wi; }
        g_Wbig[i]  = W[d*(2*Dd) + k];
        g_WbigX[i] = W[d*(2*Dd) + Dd + k];
        if (i < NC) {
            const float* bb; int db;
            if (i < 1536) { int j = i >> 9; db = i & 511; bb = (j==0)?b1r:(j==1)?b1w:bf; }
            else          { int t = i - 1536; db = t >> 1; bb = (t&1)?bc:bi; }
            g_bstack[i] = bb[db];
        }
    }
}

// ---------------- tf32 mma.sync GEMM, ldmatrix feeds, 4-stage cp.async ---------------
// epi 0: xterm   epi 1: main (scores / F / P)   epi 2: fin->out   epi 3: sub->out
__global__ void __launch_bounds__(256,1)
gemm_t(int epi, const float* __restrict__ Aext, const float* __restrict__ Bext,
       const float* __restrict__ biasExt,
       const float* __restrict__ w2r, const float* __restrict__ w2w,
       float* __restrict__ out)
{
    extern __shared__ float sm[];
    const uint32_t s0 = smem_u32(sm);

    const int tid  = threadIdx.x;
    const int lane = tid & 31, wid = tid >> 5;
    const int wm = wid & 3, wn = wid >> 2;      // 4x2 warp grid, warp tile 32x64
    const int qrow = lane >> 2;
    const int qcol = (lane & 3) * 2;
    const int row0 = blockIdx.y * BM;
    const int n0   = blockIdx.x * BN;

    const float* A  = (epi==2) ? g_subvec : (epi==3) ? g_mem : Aext;
    const float* Bw = (epi==0) ? g_WbigX  : (epi==1) ? g_Wbig : Bext;
    const float* bias = (epi==0) ? g_bstack : biasExt;

    const float* Arow = A  + (size_t)row0 * Dd;
    const float* Brow = Bw + (size_t)n0   * Dd;

    float acc[2][8][4];
#pragma unroll
    for (int mt=0;mt<2;mt++)
#pragma unroll
        for (int nt=0;nt<8;nt++)
#pragma unroll
            for (int q=0;q<4;q++) acc[mt][nt][q]=0.f;

    // per-thread ldmatrix offsets (bytes)
    uint32_t offA[2], offB[4];
#pragma unroll
    for (int mt=0;mt<2;mt++)
        offA[mt] = ((wm*32 + mt*16 + (lane&15))*36 + ((lane>>4)<<2)) * 4;
#pragma unroll
    for (int p=0;p<4;p++)
        offB[p] = ((wn*64 + p*16 + (((lane>>4)&1)<<3) + (lane&7))*36 + (((lane>>3)&1)<<2)) * 4;

#define LOADC(kc, slot) do {                                                  \
    int k0 = (kc)*BK;                                                         \
    _Pragma("unroll")                                                         \
    for (int j=0;j<4;j++){                                                    \
        int idx = j*256 + tid;                                                \
        int r = idx >> 3, c = idx & 7;                                        \
        const float* ga = Arow + (size_t)r*Dd + k0 + c*4;                     \
        const float* gb = Brow + (size_t)r*Dd + k0 + c*4;                     \
        uint32_t sa = s0 + (uint32_t)(((slot)*SFLT + r*36 + c*4)*4);          \
        uint32_t sb = s0 + (uint32_t)(((STG*SFLT) + (slot)*SFLT + r*36 + c*4)*4); \
        asm volatile("cp.async.cg.shared.global [%0],[%1],16;" :: "r"(sa), "l"(ga)); \
        asm volatile("cp.async.cg.shared.global [%0],[%1],16;" :: "r"(sb), "l"(gb)); \
    }                                                                         \
    asm volatile("cp.async.commit_group;" ::: "memory");                      \
} while(0)

    LOADC(0,0); LOADC(1,1); LOADC(2,2);

    for (int i = 0; i < NKCH; i++) {
        int slot = i & 3;
        if (i + 3 < NKCH) { asm volatile("cp.async.wait_group 2;" ::: "memory"); }
        else              { asm volatile("cp.async.wait_group 0;" ::: "memory"); }
        __syncthreads();
        if (i + 3 < NKCH) LOADC(i + 3, (i + 3) & 3);

        uint32_t abase = s0 + (uint32_t)(slot*SFLT*4);
        uint32_t bbase = s0 + (uint32_t)((STG*SFLT + slot*SFLT)*4);
#pragma unroll
        for (int s = 0; s < 4; s++) {
            uint32_t a[2][4], b[8][2];
            ldmx4(a[0], abase + offA[0] + s*32);
            ldmx4(a[1], abase + offA[1] + s*32);
#pragma unroll
            for (int p=0;p<4;p++){
                uint32_t t[4];
                ldmx4(t, bbase + offB[p] + s*32);
                b[2*p][0]=t[0]; b[2*p][1]=t[1]; b[2*p+1][0]=t[2]; b[2*p+1][1]=t[3];
            }
#pragma unroll
            for (int mt=0;mt<2;mt++)
#pragma unroll
                for (int nt=0;nt<8;nt++) mma8(acc[mt][nt], a[mt], b[nt]);
        }
    }
#undef LOADC

    // ---------------- epilogue ---------------------------------------------------
    const int jt = n0 >> 9;     // epi1: 0=r 1=w 2=F 3,4=IC region

    __syncthreads();
    float* xts = sm;            // [2][128] xterm slice (epi1)
    float* w2s = sm + 256;      // [128]    w2 slice    (epi1 scores)
    if (epi == 1) {
        int bloc = tid >> 7, cl = tid & 127;
        xts[tid] = g_xterm[(size_t)((row0 >> 6) + bloc) * NC + n0 + cl];
        if (jt < 2 && tid < 128) w2s[tid] = ((jt==0)?w2r:w2w)[(n0 & 511) + tid];
    }
    __syncthreads();

    if (epi == 1 && jt < 2) {
        float* dstp = (jt == 0) ? g_sRp : g_sWp;
        int nblk2 = ((n0 & 511) >> 7) * 2 + wn;
#pragma unroll
        for (int mt=0;mt<2;mt++){
            int r0g = row0 + wm*32 + mt*16 + qrow;
            const float* x0 = xts + ((r0g >> 6) & 1) * 128;
            const float* x1 = xts + (((r0g + 8) >> 6) & 1) * 128;
            float sp0 = 0.f, sp1 = 0.f;
#pragma unroll
            for (int nt=0;nt<8;nt++){
                int cl = wn*64 + nt*8 + qcol;
                float w0 = w2s[cl], w1 = w2s[cl+1];
                sp0 += fmaxf(acc[mt][nt][0]+x0[cl],0.f)*w0 + fmaxf(acc[mt][nt][1]+x0[cl+1],0.f)*w1;
                sp1 += fmaxf(acc[mt][nt][2]+x1[cl],0.f)*w0 + fmaxf(acc[mt][nt][3]+x1[cl+1],0.f)*w1;
            }
            sp0 += __shfl_xor_sync(0xffffffffu, sp0, 1);
            sp0 += __shfl_xor_sync(0xffffffffu, sp0, 2);
            sp1 += __shfl_xor_sync(0xffffffffu, sp1, 1);
            sp1 += __shfl_xor_sync(0xffffffffu, sp1, 2);
            if ((lane & 3) == 0) {
                dstp[(size_t)r0g*8 + nblk2]     = sp0;
                dstp[(size_t)(r0g+8)*8 + nblk2] = sp1;
            }
        }
        return;
    }

#pragma unroll
    for (int mt=0;mt<2;mt++){
        int r0g = row0 + wm*32 + mt*16 + qrow;
#pragma unroll
        for (int h=0;h<2;h++){
            int row = r0g + h*8;
#pragma unroll
            for (int nt=0;nt<8;nt++){
                int cl = wn*64 + nt*8 + qcol;
                int cg = n0 + cl;
                float c0 = acc[mt][nt][h*2+0];
                float c1 = acc[mt][nt][h*2+1];
                if (epi == 0) {
                    float2 o = { c0 + bias[cg], c1 + bias[cg+1] };
                    *(float2*)(g_xterm + (size_t)row*NC + cg) = o;
                } else if (epi == 1) {
                    const float* xr = xts + ((row >> 6) & 1) * 128;
                    float z0 = c0 + xr[cl];
                    float z1 = c1 + xr[cl+1];
                    if (jt == 2) {
                        float2 o = { fsig(z0), fsig(z1) };
                        *(float2*)(g_F + (size_t)row*Dd + (cg & 511)) = o;
                    } else {
                        g_P[(size_t)row*Dd + ((cg - 1536) >> 1)] = fsig(z0) * ftanh(z1);
                    }
                } else {
                    size_t ob = (epi == 2) ? (size_t)row * (65*Dd)
                                           : ((size_t)(row >> 6) * 65 + 1 + (row & 63)) * Dd;
                    float2 o = { ftanh(c0 + bias[cg]), ftanh(c1 + bias[cg+1]) };
                    *(float2*)(out + ob + cg) = o;
                }
            }
        }
    }
}

// ---------------- softmax over M=64 ---------------------------------------------
__global__ void softmax_k() {
    int b = blockIdx.x, m = threadIdx.x;
    int row = b*64 + m;
    float sr = 0.f, sw = 0.f;
#pragma unroll
    for (int p=0;p<8;p++){ sr += g_sRp[(size_t)row*8+p]; sw += g_sWp[(size_t)row*8+p]; }

    __shared__ float sh[64];
    sh[m] = sr; __syncthreads();
    for (int s=32;s>0;s>>=1){ if(m<s) sh[m]=fmaxf(sh[m],sh[m+s]); __syncthreads(); }
    float mxr = sh[0]; __syncthreads();
    float er = expf(sr - mxr);
    sh[m] = er; __syncthreads();
    for (int s=32;s>0;s>>=1){ if(m<s) sh[m]+=sh[m+s]; __syncthreads(); }
    float sumr = sh[0]; __syncthreads();
    g_simr[row] = er / sumr;

    sh[m] = sw; __syncthreads();
    for (int s=32;s>0;s>>=1){ if(m<s) sh[m]=fmaxf(sh[m],sh[m+s]); __syncthreads(); }
    float mxw = sh[0]; __syncthreads();
    float ew = expf(sw - mxw);
    sh[m] = ew; __syncthreads();
    for (int s=32;s>0;s>>=1){ if(m<s) sh[m]+=sh[m+s]; __syncthreads(); }
    float sumw = sh[0]; __syncthreads();
    g_simw[row] = ew / sumw;
}

// ---------------- sub_vec = sum_m sub_memory * sim_r ------------------------------
__global__ void subvec_k(const float* __restrict__ sub) {
    int b = blockIdx.x, d = threadIdx.x;
    __shared__ float ss[64];
    if (d < 64) ss[d] = g_simr[b*64 + d];
    __syncthreads();
    const float* base = sub + (size_t)b*64*512 + d;
    float acc = 0.f;
#pragma unroll
    for (int m=0;m<64;m++) acc += base[m*512] * ss[m];
    g_subvec[b*512 + d] = acc;
}

// ---------------- mem = (1 - sw*F)*sub + P*sw --------------------------------------
__global__ void mem_k(const float* __restrict__ sub) {
    int i4 = blockIdx.x*blockDim.x + threadIdx.x;
    const int n4 = NROWS*(Dd/4);
    if (i4 >= n4) return;
    int r = i4 >> 7;
    float sw = g_simw[r];
    float4 s  = ((const float4*)sub)[i4];
    float4 f  = ((const float4*)g_F)[i4];
    float4 p  = ((const float4*)g_P)[i4];
    float4 o;
    o.x = (1.f - sw*f.x)*s.x + p.x*sw;
    o.y = (1.f - sw*f.y)*s.y + p.y*sw;
    o.z = (1.f - sw*f.z)*s.z + p.z*sw;
    o.w = (1.f - sw*f.w)*s.w + p.w*sw;
    ((float4*)g_mem)[i4] = o;
}

// ---------------- launch ------------------------------------------------------------
extern "C" void kernel_launch(void* const* d_in, const int* in_sizes, int n_in,
                              void* d_out, int out_size)
{
    const float* x    = (const float*)d_in[0];
    const float* sub  = (const float*)d_in[1];
    const float* W1r  = (const float*)d_in[2];
    const float* b1r  = (const float*)d_in[3];
    const float* W2r  = (const float*)d_in[4];
    const float* W1w  = (const float*)d_in[6];
    const float* b1w  = (const float*)d_in[7];
    const float* W2w  = (const float*)d_in[8];
    const float* Wf   = (const float*)d_in[10];
    const float* bf   = (const float*)d_in[11];
    const float* Wi   = (const float*)d_in[12];
    const float* bi   = (const float*)d_in[13];
    const float* Wc   = (const float*)d_in[14];
    const float* bc   = (const float*)d_in[15];
    const float* Wsub = (const float*)d_in[16];
    const float* bsub = (const float*)d_in[17];
    const float* Wfin = (const float*)d_in[18];
    const float* bfin = (const float*)d_in[19];
    float* out = (float*)d_out;

    cudaFuncSetAttribute(gemm_t, cudaFuncAttributeMaxDynamicSharedMemorySize, SMEM_BYTES);

    prep_k<<<(NC*Dd + 255)/256, 256>>>(W1r, W1w, Wf, Wi, Wc, b1r, b1w, bf, bi, bc);

    // xterm = x @ WX^T + bstack
    gemm_t<<<dim3(NC/BN, Bb/BM), 256, SMEM_BYTES>>>(0, x, nullptr, nullptr, nullptr, nullptr, nullptr);

    // main: sub_memory @ Wbig^T + xterm -> score partials, F, P
    gemm_t<<<dim3(NC/BN, NROWS/BM), 256, SMEM_BYTES>>>(1, sub, nullptr, nullptr, W2r, W2w, nullptr);

    softmax_k<<<Bb, 64>>>();
    subvec_k<<<Bb, 512>>>(sub);
    mem_k<<<(NROWS*(Dd/4) + 255)/256, 256>>>(sub);

    // read_vec = tanh(sub_vec @ Wfin^T + bfin) -> out[b,0,:]
    gemm_t<<<dim3(Dd/BN, Bb/BM), 256, SMEM_BYTES>>>(2, nullptr, Wfin, bfin, nullptr, nullptr, out);

    // new_mem = tanh(mem @ Wsub^T + bsub) -> out[b,1+m,:]
    gemm_t<<<dim3(Dd/BN, NROWS/BM), 256, SMEM_BYTES>>>(3, nullptr, Wsub, bsub, nullptr, nullptr, out);
}

// round 8
// speedup vs baseline: 3.8394x; 1.1429x over previous
#include <cuda_runtime.h>
#include <math.h>
#include <stdint.h>

#define Bb 2048
#define Mm 64
#define Dd 512
#define NROWS (Bb*Mm)     // 131072
#define NC    2560        // stacked cols: [zr | zw | zF | interleaved(zI,zC)]
#define BM    128
#define BN    256
#define BK    32
#define NKCH  (Dd/BK)     // 16
#define STG   3
#define PAD   36          // floats per smem row (144B)
#define ASTG  (128*PAD)   // 4608 floats
#define BSTG  (256*PAD)   // 9216 floats
#define SMEM_BYTES (STG*(ASTG+BSTG)*4)   // 165888

// ---------------- scratch (device globals) -----------------------------------------
__device__ float g_Wbig [NC*Dd];
__device__ float g_WbigX[NC*Dd];
__device__ float g_bstack[NC];
__device__ float g_xterm[Bb*NC];
__device__ float g_F[(size_t)NROWS*Dd];
__device__ float g_P[(size_t)NROWS*Dd];      // sigmoid(zI)*tanh(zC)
__device__ float g_mem[(size_t)NROWS*Dd];
__device__ float g_subvec[Bb*Dd];
__device__ float g_sRp[NROWS*8];
__device__ float g_sWp[NROWS*8];
__device__ float g_simr[NROWS];
__device__ float g_simw[NROWS];

__device__ __forceinline__ uint32_t smem_u32(const void* p){
    uint32_t a;
    asm("{ .reg .u64 t; cvta.to.shared.u64 t, %1; cvt.u32.u64 %0, t; }" : "=r"(a) : "l"(p));
    return a;
}
__device__ __forceinline__ float fsig(float z){ return __fdividef(1.f, 1.f + __expf(-z)); }
__device__ __forceinline__ float ftanh(float z){ return __fdividef(2.f, 1.f + __expf(-2.f*z)) - 1.f; }
__device__ __forceinline__ void ldmx4(uint32_t* r, uint32_t addr){
    asm volatile("ldmatrix.sync.aligned.m8n8.x4.shared.b16 {%0,%1,%2,%3}, [%4];"
        : "=r"(r[0]), "=r"(r[1]), "=r"(r[2]), "=r"(r[3]) : "r"(addr));
}
__device__ __forceinline__ void mma8(float* d, const uint32_t* a, const uint32_t* b){
    asm volatile(
        "mma.sync.aligned.m16n8k8.row.col.f32.tf32.tf32.f32 "
        "{%0,%1,%2,%3}, {%4,%5,%6,%7}, {%8,%9}, {%0,%1,%2,%3};"
        : "+f"(d[0]), "+f"(d[1]), "+f"(d[2]), "+f"(d[3])
        : "r"(a[0]), "r"(a[1]), "r"(a[2]), "r"(a[3]), "r"(b[0]), "r"(b[1]));
}

// ---------------- weight stacking: [Wr | Ww | WF | interleave(WI,WC)] ----------------
__global__ void prep_k(const float* __restrict__ W1r, const float* __restrict__ W1w,
                       const float* __restrict__ Wf,  const float* __restrict__ Wi,
                       const float* __restrict__ Wc,
                       const float* __restrict__ b1r, const float* __restrict__ b1w,
                       const float* __restrict__ bf,  const float* __restrict__ bi,
                       const float* __restrict__ bc)
{
    int i = blockIdx.x*blockDim.x + threadIdx.x;
    if (i < NC*Dd) {
        int c = i >> 9, k = i & 511;
        const float* W; int d;
        if (c < 1536) { int j = c >> 9; d = c & 511; W = (j==0)?W1r:(j==1)?W1w:Wf; }
        else          { int t = c - 1536; d = t >> 1; W = (t&1)?Wc:Wi; }
        g_Wbig[i]  = W[d*(2*Dd) + k];
        g_WbigX[i] = W[d*(2*Dd) + Dd + k];
        if (i < NC) {
            const float* bb; int db;
            if (i < 1536) { int j = i >> 9; db = i & 511; bb = (j==0)?b1r:(j==1)?b1w:bf; }
            else          { int t = i - 1536; db = t >> 1; bb = (t&1)?bc:bi; }
            g_bstack[i] = bb[db];
        }
    }
}

// ---------------- tf32 mma.sync GEMM, 64x64 warp tiles, 3-stage cp.async -------------
// epi 0: xterm   epi 1: main (scores / F / P)   epi 2: fin->out   epi 3: sub->out
__global__ void __launch_bounds__(256,1)
gemm_t(int epi, const float* __restrict__ Aext, const float* __restrict__ Bext,
       const float* __restrict__ bias,
       const float* __restrict__ w2r, const float* __restrict__ w2w,
       float* __restrict__ out)
{
    extern __shared__ float sm[];
    const uint32_t s0 = smem_u32(sm);

    const int tid  = threadIdx.x;
    const int lane = tid & 31, wid = tid >> 5;
    const int wm = wid & 1, wn = wid >> 1;        // 2x4 warp grid, warp tile 64x64
    const int qrow = lane >> 2;
    const int qcol = (lane & 3) * 2;
    const int row0 = blockIdx.y * BM;
    const int n0   = blockIdx.x * BN;

    const float* A  = (epi==1) ? Aext : (epi==0) ? Aext : (epi==2) ? g_subvec : g_mem;
    const float* Bw = (epi==0) ? g_WbigX : (epi==1) ? g_Wbig : Bext;

    const float* Arow = A  + (size_t)row0 * Dd;
    const float* Brow = Bw + (size_t)n0   * Dd;

    float acc[4][8][4];
#pragma unroll
    for (int mt=0;mt<4;mt++)
#pragma unroll
        for (int nt=0;nt<8;nt++)
#pragma unroll
            for (int q=0;q<4;q++) acc[mt][nt][q]=0.f;

    // ldmatrix byte offsets (tf32 fragments via b16 x4)
    uint32_t offA[4], offB[4];
#pragma unroll
    for (int mt=0;mt<4;mt++)
        offA[mt] = (uint32_t)(((wm*64 + mt*16 + (lane&15))*PAD + ((lane>>4)<<2)) * 4);
#pragma unroll
    for (int p=0;p<4;p++)
        offB[p] = (uint32_t)(((wn*64 + p*16 + (((lane>>4)&1)<<3) + (lane&7))*PAD
                              + (((lane>>3)&1)<<2)) * 4);

#define LOADC(kc, slot) do {                                                     \
    int k0 = (kc)*BK;                                                            \
    _Pragma("unroll")                                                            \
    for (int j=0;j<4;j++){                                                       \
        int idx = j*256 + tid;                                                   \
        int r = idx >> 3, seg = idx & 7;                                         \
        const float* ga = Arow + (size_t)r*Dd + k0 + seg*4;                      \
        uint32_t sa = s0 + (uint32_t)(((slot)*ASTG + r*PAD + seg*4)*4);          \
        asm volatile("cp.async.cg.shared.global [%0],[%1],16;" :: "r"(sa), "l"(ga)); \
    }                                                                            \
    _Pragma("unroll")                                                            \
    for (int j=0;j<8;j++){                                                       \
        int idx = j*256 + tid;                                                   \
        int r = idx >> 3, seg = idx & 7;                                         \
        const float* gb = Brow + (size_t)r*Dd + k0 + seg*4;                      \
        uint32_t sb = s0 + (uint32_t)(((STG*ASTG) + (slot)*BSTG + r*PAD + seg*4)*4); \
        asm volatile("cp.async.cg.shared.global [%0],[%1],16;" :: "r"(sb), "l"(gb)); \
    }                                                                            \
    asm volatile("cp.async.commit_group;" ::: "memory");                         \
} while(0)

    LOADC(0,0); LOADC(1,1);

    int slot = 0;
    for (int i = 0; i < NKCH; i++) {
        if (i + 2 < NKCH) { asm volatile("cp.async.wait_group 1;" ::: "memory"); }
        else              { asm volatile("cp.async.wait_group 0;" ::: "memory"); }
        __syncthreads();
        if (i + 2 < NKCH) {
            int ns = slot + 2; if (ns >= STG) ns -= STG;
            LOADC(i + 2, ns);
        }

        uint32_t abase = s0 + (uint32_t)(slot*ASTG*4);
        uint32_t bbase = s0 + (uint32_t)((STG*ASTG + slot*BSTG)*4);
#pragma unroll
        for (int s = 0; s < 4; s++) {               // four k8 steps
            uint32_t a[4][4], bt[4][4];
#pragma unroll
            for (int mt=0;mt<4;mt++) ldmx4(a[mt], abase + offA[mt] + s*32);
#pragma unroll
            for (int p=0;p<4;p++)   ldmx4(bt[p], bbase + offB[p] + s*32);
#pragma unroll
            for (int mt=0;mt<4;mt++)
#pragma unroll
                for (int p=0;p<4;p++){
                    mma8(acc[mt][2*p],   a[mt], &bt[p][0]);
                    mma8(acc[mt][2*p+1], a[mt], &bt[p][2]);
                }
        }
        if (++slot >= STG) slot = 0;
    }
#undef LOADC

    // ---------------- epilogue --------------------------------------------------------
    const int jt = n0 >> 9;     // epi1: 0,1=scores(r,w) 2=F 3,4=IC

    __syncthreads();
    float* xts = sm;            // [2][256] xterm slices (2 batches in this row panel)
    float* w2s = sm + 512;      // [256]
    if (epi == 1) {
#pragma unroll
        for (int t=0;t<2;t++){
            int idx = t*256 + tid;
            int bloc = idx >> 8, cl = idx & 255;
            xts[idx] = g_xterm[(size_t)((row0 >> 6) + bloc) * NC + n0 + cl];
        }
        if (jt < 2) w2s[tid] = ((jt==0)?w2r:w2w)[(n0 & 511) + tid];
    }
    __syncthreads();

    if (epi == 1 && jt < 2) {
        float* dstp = (jt == 0) ? g_sRp : g_sWp;
        const int pidx = ((n0 >> 8) & 1) * 4 + wn;      // 0..7
        const float* x0 = xts + wm * 256;
#pragma unroll
        for (int mt=0;mt<4;mt++){
            int r0g = row0 + wm*64 + mt*16 + qrow;
            float sp0 = 0.f, sp1 = 0.f;
#pragma unroll
            for (int nt=0;nt<8;nt++){
                int cl = wn*64 + nt*8 + qcol;
                float w0 = w2s[cl], w1 = w2s[cl+1];
                sp0 += fmaxf(acc[mt][nt][0]+x0[cl],0.f)*w0 + fmaxf(acc[mt][nt][1]+x0[cl+1],0.f)*w1;
                sp1 += fmaxf(acc[mt][nt][2]+x0[cl],0.f)*w0 + fmaxf(acc[mt][nt][3]+x0[cl+1],0.f)*w1;
            }
            sp0 += __shfl_xor_sync(0xffffffffu, sp0, 1);
            sp0 += __shfl_xor_sync(0xffffffffu, sp0, 2);
            sp1 += __shfl_xor_sync(0xffffffffu, sp1, 1);
            sp1 += __shfl_xor_sync(0xffffffffu, sp1, 2);
            if ((lane & 3) == 0) {
                dstp[(size_t)r0g*8 + pidx]     = sp0;
                dstp[(size_t)(r0g+8)*8 + pidx] = sp1;
            }
        }
        return;
    }

#pragma unroll
    for (int mt=0;mt<4;mt++){
        int r0g = row0 + wm*64 + mt*16 + qrow;
#pragma unroll
        for (int h=0;h<2;h++){
            int row = r0g + h*8;
#pragma unroll
            for (int nt=0;nt<8;nt++){
                int cl = wn*64 + nt*8 + qcol;
                int cg = n0 + cl;
                float c0 = acc[mt][nt][h*2+0];
                float c1 = acc[mt][nt][h*2+1];
                if (epi == 0) {
                    float2 o = { c0 + bias[cg], c1 + bias[cg+1] };
                    *(float2*)(g_xterm + (size_t)row*NC + cg) = o;
                } else if (epi == 1) {
                    const float* xr = xts + wm * 256;
                    float z0 = c0 + xr[cl];
                    float z1 = c1 + xr[cl+1];
                    if (jt == 2) {
                        float2 o = { fsig(z0), fsig(z1) };
                        *(float2*)(g_F + (size_t)row*Dd + (cg - 1024)) = o;
                    } else {
                        g_P[(size_t)row*Dd + ((cg - 1536) >> 1)] = fsig(z0) * ftanh(z1);
                    }
                } else {
                    size_t ob = (epi == 2) ? (size_t)row * (65*Dd)
                                           : ((size_t)(row >> 6) * 65 + 1 + (row & 63)) * Dd;
                    float2 o = { ftanh(c0 + bias[cg]), ftanh(c1 + bias[cg+1]) };
                    *(float2*)(out + ob + cg) = o;
                }
            }
        }
    }
}

// ---------------- softmax over M=64 ---------------------------------------------------
__global__ void softmax_k() {
    int b = blockIdx.x, m = threadIdx.x;
    int row = b*64 + m;
    float sr = 0.f, sw = 0.f;
#pragma unroll
    for (int p=0;p<8;p++){ sr += g_sRp[(size_t)row*8+p]; sw += g_sWp[(size_t)row*8+p]; }

    __shared__ float sh[64];
    sh[m] = sr; __syncthreads();
    for (int s=32;s>0;s>>=1){ if(m<s) sh[m]=fmaxf(sh[m],sh[m+s]); __syncthreads(); }
    float mxr = sh[0]; __syncthreads();
    float er = expf(sr - mxr);
    sh[m] = er; __syncthreads();
    for (int s=32;s>0;s>>=1){ if(m<s) sh[m]+=sh[m+s]; __syncthreads(); }
    float sumr = sh[0]; __syncthreads();
    g_simr[row] = er / sumr;

    sh[m] = sw; __syncthreads();
    for (int s=32;s>0;s>>=1){ if(m<s) sh[m]=fmaxf(sh[m],sh[m+s]); __syncthreads(); }
    float mxw = sh[0]; __syncthreads();
    float ew = expf(sw - mxw);
    sh[m] = ew; __syncthreads();
    for (int s=32;s>0;s>>=1){ if(m<s) sh[m]+=sh[m+s]; __syncthreads(); }
    float sumw = sh[0]; __syncthreads();
    g_simw[row] = ew / sumw;
}

// ---------------- sub_vec = sum_m sub_memory * sim_r -----------------------------------
__global__ void subvec_k(const float* __restrict__ sub) {
    int b = blockIdx.x, d = threadIdx.x;
    __shared__ float ss[64];
    if (d < 64) ss[d] = g_simr[b*64 + d];
    __syncthreads();
    const float* base = sub + (size_t)b*64*512 + d;
    float acc = 0.f;
#pragma unroll
    for (int m=0;m<64;m++) acc += base[m*512] * ss[m];
    g_subvec[b*512 + d] = acc;
}

// ---------------- mem = (1 - sw*F)*sub + P*sw -------------------------------------------
__global__ void mem_k(const float* __restrict__ sub) {
    int i4 = blockIdx.x*blockDim.x + threadIdx.x;
    const int n4 = NROWS*(Dd/4);
    if (i4 >= n4) return;
    int r = i4 >> 7;
    float sw = g_simw[r];
    float4 s  = ((const float4*)sub)[i4];
    float4 f  = ((const float4*)g_F)[i4];
    float4 p  = ((const float4*)g_P)[i4];
    float4 o;
    o.x = (1.f - sw*f.x)*s.x + p.x*sw;
    o.y = (1.f - sw*f.y)*s.y + p.y*sw;
    o.z = (1.f - sw*f.z)*s.z + p.z*sw;
    o.w = (1.f - sw*f.w)*s.w + p.w*sw;
    ((float4*)g_mem)[i4] = o;
}

// ---------------- launch -------------------------------------------------------------------
extern "C" void kernel_launch(void* const* d_in, const int* in_sizes, int n_in,
                              void* d_out, int out_size)
{
    const float* x    = (const float*)d_in[0];
    const float* sub  = (const float*)d_in[1];
    const float* W1r  = (const float*)d_in[2];
    const float* b1r  = (const float*)d_in[3];
    const float* W2r  = (const float*)d_in[4];
    const float* W1w  = (const float*)d_in[6];
    const float* b1w  = (const float*)d_in[7];
    const float* W2w  = (const float*)d_in[8];
    const float* Wf   = (const float*)d_in[10];
    const float* bf   = (const float*)d_in[11];
    const float* Wi   = (const float*)d_in[12];
    const float* bi   = (const float*)d_in[13];
    const float* Wc   = (const float*)d_in[14];
    const float* bc   = (const float*)d_in[15];
    const float* Wsub = (const float*)d_in[16];
    const float* bsub = (const float*)d_in[17];
    const float* Wfin = (const float*)d_in[18];
    const float* bfin = (const float*)d_in[19];
    float* out = (float*)d_out;

    cudaFuncSetAttribute(gemm_t, cudaFuncAttributeMaxDynamicSharedMemorySize, SMEM_BYTES);

    prep_k<<<(NC*Dd + 255)/256, 256>>>(W1r, W1w, Wf, Wi, Wc, b1r, b1w, bf, bi, bc);

    // xterm = x @ WX^T + bstack
    gemm_t<<<dim3(NC/BN, Bb/BM), 256, SMEM_BYTES>>>(0, x, nullptr, g_bstack, nullptr, nullptr, nullptr);

    // main: sub_memory @ Wbig^T + xterm -> score partials, F, P
    gemm_t<<<dim3(NC/BN, NROWS/BM), 256, SMEM_BYTES>>>(1, sub, nullptr, nullptr, W2r, W2w, nullptr);

    softmax_k<<<Bb, 64>>>();
    subvec_k<<<Bb, 512>>>(sub);
    mem_k<<<(NROWS*(Dd/4) + 255)/256, 256>>>(sub);

    // read_vec = tanh(sub_vec @ Wfin^T + bfin) -> out[b,0,:]
    gemm_t<<<dim3(Dd/BN, Bb/BM), 256, SMEM_BYTES>>>(2, nullptr, Wfin, bfin, nullptr, nullptr, out);

    // new_mem = tanh(mem @ Wsub^T + bsub) -> out[b,1+m,:]
    gemm_t<<<dim3(Dd/BN, NROWS/BM), 256, SMEM_BYTES>>>(3, nullptr, Wsub, bsub, nullptr, nullptr, out);
}

// round 9
// speedup vs baseline: 3.9594x; 1.0313x over previous
#include <cuda_runtime.h>
#include <math.h>
#include <stdint.h>

#define Bb 2048
#define Mm 64
#define Dd 512
#define NROWS (Bb*Mm)     // 131072
#define NC    2560        // stacked cols: [zr | zw | zF | interleaved(zI,zC)]
#define BM    128
#define BN    256
#define BK    64
#define NKC   (Dd/BK)     // 8
#define STG   2
#define PAD   68          // floats per smem row (272B; r*68 mod 32 = r*4 -> conflict-free LDSM)
#define ASTG  (128*PAD)   // 8704 floats
#define BSTG  (256*PAD)   // 17408 floats
#define SMEM_BYTES (STG*(ASTG+BSTG)*4)   // 208896

// ---------------- scratch (device globals) -----------------------------------------
__device__ float g_Wbig [NC*Dd];
__device__ float g_WbigX[NC*Dd];
__device__ float g_bstack[NC];
__device__ float g_xterm[Bb*NC];
__device__ float g_F[(size_t)NROWS*Dd];
__device__ float g_P[(size_t)NROWS*Dd];      // sigmoid(zI)*tanh(zC)
__device__ float g_subvec[Bb*Dd];
__device__ float g_sRp[NROWS*8];
__device__ float g_sWp[NROWS*8];
__device__ float g_simr[NROWS];
__device__ float g_simw[NROWS];

__device__ __forceinline__ uint32_t smem_u32(const void* p){
    uint32_t a;
    asm("{ .reg .u64 t; cvta.to.shared.u64 t, %1; cvt.u32.u64 %0, t; }" : "=r"(a) : "l"(p));
    return a;
}
__device__ __forceinline__ float fsig(float z){ return __fdividef(1.f, 1.f + __expf(-z)); }
__device__ __forceinline__ float ftanh(float z){ return __fdividef(2.f, 1.f + __expf(-2.f*z)) - 1.f; }
__device__ __forceinline__ void ldmx4(uint32_t* r, uint32_t addr){
    asm volatile("ldmatrix.sync.aligned.m8n8.x4.shared.b16 {%0,%1,%2,%3}, [%4];"
        : "=r"(r[0]), "=r"(r[1]), "=r"(r[2]), "=r"(r[3]) : "r"(addr));
}
__device__ __forceinline__ void mma8(float* d, const uint32_t* a, const uint32_t* b){
    asm volatile(
        "mma.sync.aligned.m16n8k8.row.col.f32.tf32.tf32.f32 "
        "{%0,%1,%2,%3}, {%4,%5,%6,%7}, {%8,%9}, {%0,%1,%2,%3};"
        : "+f"(d[0]), "+f"(d[1]), "+f"(d[2]), "+f"(d[3])
        : "r"(a[0]), "r"(a[1]), "r"(a[2]), "r"(a[3]), "r"(b[0]), "r"(b[1]));
}

// ---------------- weight stacking: [Wr | Ww | WF | interleave(WI,WC)] ----------------
__global__ void prep_k(const float* __restrict__ W1r, const float* __restrict__ W1w,
                       const float* __restrict__ Wf,  const float* __restrict__ Wi,
                       const float* __restrict__ Wc,
                       const float* __restrict__ b1r, const float* __restrict__ b1w,
                       const float* __restrict__ bf,  const float* __restrict__ bi,
                       const float* __restrict__ bc)
{
    int i = blockIdx.x*blockDim.x + threadIdx.x;
    if (i < NC*Dd) {
        int c = i >> 9, k = i & 511;
        const float* W; int d;
        if (c < 1536) { int j = c >> 9; d = c & 511; W = (j==0)?W1r:(j==1)?W1w:Wf; }
        else          { int t = c - 1536; d = t >> 1; W = (t&1)?Wc:Wi; }
        g_Wbig[i]  = W[d*(2*Dd) + k];
        g_WbigX[i] = W[d*(2*Dd) + Dd + k];
        if (i < NC) {
            const float* bb; int db;
            if (i < 1536) { int j = i >> 9; db = i & 511; bb = (j==0)?b1r:(j==1)?b1w:bf; }
            else          { int t = i - 1536; db = t >> 1; bb = (t&1)?bc:bi; }
            g_bstack[i] = bb[db];
        }
    }
}

// ---------------- tf32 mma.sync GEMM, 64x64 warp tiles, BK=64, 2-stage ----------------
// epi 0: xterm   epi 1: main (scores / F / P)   epi 2: fin->out
// epi 3: sub->out with FUSED gating: A = (1 - sw*F)*sub + P*sw computed in the loader
__global__ void __launch_bounds__(256,1)
gemm_t(int epi, const float* __restrict__ Aext, const float* __restrict__ Bext,
       const float* __restrict__ bias,
       const float* __restrict__ w2r, const float* __restrict__ w2w,
       float* __restrict__ out)
{
    extern __shared__ float sm[];
    const uint32_t s0 = smem_u32(sm);

    const int tid  = threadIdx.x;
    const int lane = tid & 31, wid = tid >> 5;
    const int wm = wid & 1, wn = wid >> 1;        // 2x4 warp grid, warp tile 64x64
    const int qrow = lane >> 2;
    const int qcol = (lane & 3) * 2;
    const int row0 = blockIdx.y * BM;
    const int n0   = blockIdx.x * BN;

    const float* A  = (epi==2) ? g_subvec : Aext;     // epi3: Aext = sub (gated in loader)
    const float* Bw = (epi==0) ? g_WbigX : (epi==1) ? g_Wbig : Bext;

    const float* Arow = A  + (size_t)row0 * Dd;
    const float* Brow = Bw + (size_t)n0   * Dd;

    float acc[4][8][4];
#pragma unroll
    for (int mt=0;mt<4;mt++)
#pragma unroll
        for (int nt=0;nt<8;nt++)
#pragma unroll
            for (int q=0;q<4;q++) acc[mt][nt][q]=0.f;

    // ldmatrix byte offsets (tf32 fragments via b16 x4)
    uint32_t offA[4], offB[4];
#pragma unroll
    for (int mt=0;mt<4;mt++)
        offA[mt] = (uint32_t)(((wm*64 + mt*16 + (lane&15))*PAD + ((lane>>4)<<2)) * 4);
#pragma unroll
    for (int p=0;p<4;p++)
        offB[p] = (uint32_t)(((wn*64 + p*16 + (((lane>>4)&1)<<3) + (lane&7))*PAD
                              + (((lane>>3)&1)<<2)) * 4);

// A tile via cp.async (epi != 3): 128 rows x 64 floats
#define LOADA(kc, slot) do {                                                     \
    int k0 = (kc)*BK;                                                            \
    _Pragma("unroll")                                                            \
    for (int j=0;j<8;j++){                                                       \
        int idx = j*256 + tid;                                                   \
        int r = idx >> 4, seg = idx & 15;                                        \
        const float* ga = Arow + (size_t)r*Dd + k0 + seg*4;                      \
        uint32_t sa = s0 + (uint32_t)(((slot)*ASTG + r*PAD + seg*4)*4);          \
        asm volatile("cp.async.cg.shared.global [%0],[%1],16;" :: "r"(sa), "l"(ga)); \
    } } while(0)

// A tile with fused gating (epi == 3): mem = (1 - sw*F)*sub + P*sw, via LDG + STS
#define LOADA3(kc, slot) do {                                                    \
    int k0 = (kc)*BK;                                                            \
    _Pragma("unroll")                                                            \
    for (int j=0;j<8;j++){                                                       \
        int idx = j*256 + tid;                                                   \
        int r = idx >> 4, seg = idx & 15;                                        \
        int grow = row0 + r;                                                     \
        size_t goff = (size_t)grow*Dd + k0 + seg*4;                              \
        float swv = __ldg(g_simw + grow);                                        \
        float4 s4 = *(const float4*)(Arow + (size_t)r*Dd + k0 + seg*4);          \
        float4 fv = *(const float4*)(g_F + goff);                                \
        float4 pv = *(const float4*)(g_P + goff);                                \
        float4 o;                                                                \
        o.x = (1.f - swv*fv.x)*s4.x + pv.x*swv;                                  \
        o.y = (1.f - swv*fv.y)*s4.y + pv.y*swv;                                  \
        o.z = (1.f - swv*fv.z)*s4.z + pv.z*swv;                                  \
        o.w = (1.f - swv*fv.w)*s4.w + pv.w*swv;                                  \
        *(float4*)(sm + (slot)*ASTG + r*PAD + seg*4) = o;                        \
    } } while(0)

// B tile via cp.async + commit (one group covers A cp.asyncs too)
#define LOADB(kc, slot) do {                                                     \
    int k0 = (kc)*BK;                                                            \
    _Pragma("unroll")                                                            \
    for (int j=0;j<16;j++){                                                      \
        int idx = j*256 + tid;                                                   \
        int r = idx >> 4, seg = idx & 15;                                        \
        const float* gb = Brow + (size_t)r*Dd + k0 + seg*4;                      \
        uint32_t sb = s0 + (uint32_t)(((STG*ASTG) + (slot)*BSTG + r*PAD + seg*4)*4); \
        asm volatile("cp.async.cg.shared.global [%0],[%1],16;" :: "r"(sb), "l"(gb)); \
    }                                                                            \
    asm volatile("cp.async.commit_group;" ::: "memory");                         \
} while(0)

    if (epi != 3) LOADA(0,0); else LOADA3(0,0);
    LOADB(0,0);

    for (int i = 0; i < NKC; i++) {
        int slot = i & 1;
        asm volatile("cp.async.wait_group 0;" ::: "memory");
        __syncthreads();
        if (i + 1 < NKC) {
            int ns = slot ^ 1;
            if (epi != 3) LOADA(i+1, ns); else LOADA3(i+1, ns);
            LOADB(i+1, ns);
        }

        uint32_t abase = s0 + (uint32_t)(slot*ASTG*4);
        uint32_t bbase = s0 + (uint32_t)((STG*ASTG + slot*BSTG)*4);
#pragma unroll
        for (int s = 0; s < 8; s++) {               // eight k8 steps
            uint32_t a[4][4], bt[4][4];
#pragma unroll
            for (int mt=0;mt<4;mt++) ldmx4(a[mt], abase + offA[mt] + s*32);
#pragma unroll
            for (int p=0;p<4;p++)   ldmx4(bt[p], bbase + offB[p] + s*32);
#pragma unroll
            for (int mt=0;mt<4;mt++)
#pragma unroll
                for (int p=0;p<4;p++){
                    mma8(acc[mt][2*p],   a[mt], &bt[p][0]);
                    mma8(acc[mt][2*p+1], a[mt], &bt[p][2]);
                }
        }
    }
#undef LOADA
#undef LOADA3
#undef LOADB

    // ---------------- epilogue --------------------------------------------------------
    const int jt = n0 >> 9;     // epi1: 0,1=scores(r,w) 2=F 3,4=IC

    __syncthreads();
    float* xts = sm;            // [2][256] xterm slices (2 batches in this row panel)
    float* w2s = sm + 512;      // [256]
    if (epi == 1) {
#pragma unroll
        for (int t=0;t<2;t++){
            int idx = t*256 + tid;
            int bloc = idx >> 8, cl = idx & 255;
            xts[idx] = g_xterm[(size_t)((row0 >> 6) + bloc) * NC + n0 + cl];
        }
        if (jt < 2) w2s[tid] = ((jt==0)?w2r:w2w)[(n0 & 511) + tid];
    }
    __syncthreads();

    if (epi == 1 && jt < 2) {
        float* dstp = (jt == 0) ? g_sRp : g_sWp;
        const int pidx = ((n0 >> 8) & 1) * 4 + wn;      // 0..7
        const float* x0 = xts + wm * 256;
#pragma unroll
        for (int mt=0;mt<4;mt++){
            int r0g = row0 + wm*64 + mt*16 + qrow;
            float sp0 = 0.f, sp1 = 0.f;
#pragma unroll
            for (int nt=0;nt<8;nt++){
                int cl = wn*64 + nt*8 + qcol;
                float w0 = w2s[cl], w1 = w2s[cl+1];
                sp0 += fmaxf(acc[mt][nt][0]+x0[cl],0.f)*w0 + fmaxf(acc[mt][nt][1]+x0[cl+1],0.f)*w1;
                sp1 += fmaxf(acc[mt][nt][2]+x0[cl],0.f)*w0 + fmaxf(acc[mt][nt][3]+x0[cl+1],0.f)*w1;
            }
            sp0 += __shfl_xor_sync(0xffffffffu, sp0, 1);
            sp0 += __shfl_xor_sync(0xffffffffu, sp0, 2);
            sp1 += __shfl_xor_sync(0xffffffffu, sp1, 1);
            sp1 += __shfl_xor_sync(0xffffffffu, sp1, 2);
            if ((lane & 3) == 0) {
                dstp[(size_t)r0g*8 + pidx]     = sp0;
                dstp[(size_t)(r0g+8)*8 + pidx] = sp1;
            }
        }
        return;
    }

#pragma unroll
    for (int mt=0;mt<4;mt++){
        int r0g = row0 + wm*64 + mt*16 + qrow;
#pragma unroll
        for (int h=0;h<2;h++){
            int row = r0g + h*8;
#pragma unroll
            for (int nt=0;nt<8;nt++){
                int cl = wn*64 + nt*8 + qcol;
                int cg = n0 + cl;
                float c0 = acc[mt][nt][h*2+0];
                float c1 = acc[mt][nt][h*2+1];
                if (epi == 0) {
                    float2 o = { c0 + bias[cg], c1 + bias[cg+1] };
                    *(float2*)(g_xterm + (size_t)row*NC + cg) = o;
                } else if (epi == 1) {
                    const float* xr = xts + wm * 256;
                    float z0 = c0 + xr[cl];
                    float z1 = c1 + xr[cl+1];
                    if (jt == 2) {
                        float2 o = { fsig(z0), fsig(z1) };
                        *(float2*)(g_F + (size_t)row*Dd + (cg - 1024)) = o;
                    } else {
                        g_P[(size_t)row*Dd + ((cg - 1536) >> 1)] = fsig(z0) * ftanh(z1);
                    }
                } else {
                    size_t ob = (epi == 2) ? (size_t)row * (65*Dd)
                                           : ((size_t)(row >> 6) * 65 + 1 + (row & 63)) * Dd;
                    float2 o = { ftanh(c0 + bias[cg]), ftanh(c1 + bias[cg+1]) };
                    *(float2*)(out + ob + cg) = o;
                }
            }
        }
    }
}

// ---------------- softmax over M=64 ---------------------------------------------------
__global__ void softmax_k() {
    int b = blockIdx.x, m = threadIdx.x;
    int row = b*64 + m;
    float sr = 0.f, sw = 0.f;
#pragma unroll
    for (int p=0;p<8;p++){ sr += g_sRp[(size_t)row*8+p]; sw += g_sWp[(size_t)row*8+p]; }

    __shared__ float sh[64];
    sh[m] = sr; __syncthreads();
    for (int s=32;s>0;s>>=1){ if(m<s) sh[m]=fmaxf(sh[m],sh[m+s]); __syncthreads(); }
    float mxr = sh[0]; __syncthreads();
    float er = expf(sr - mxr);
    sh[m] = er; __syncthreads();
    for (int s=32;s>0;s>>=1){ if(m<s) sh[m]+=sh[m+s]; __syncthreads(); }
    float sumr = sh[0]; __syncthreads();
    g_simr[row] = er / sumr;

    sh[m] = sw; __syncthreads();
    for (int s=32;s>0;s>>=1){ if(m<s) sh[m]=fmaxf(sh[m],sh[m+s]); __syncthreads(); }
    float mxw = sh[0]; __syncthreads();
    float ew = expf(sw - mxw);
    sh[m] = ew; __syncthreads();
    for (int s=32;s>0;s>>=1){ if(m<s) sh[m]+=sh[m+s]; __syncthreads(); }
    float sumw = sh[0]; __syncthreads();
    g_simw[row] = ew / sumw;
}

// ---------------- sub_vec = sum_m sub_memory * sim_r -----------------------------------
__global__ void subvec_k(const float* __restrict__ sub) {
    int b = blockIdx.x, d = threadIdx.x;
    __shared__ float ss[64];
    if (d < 64) ss[d] = g_simr[b*64 + d];
    __syncthreads();
    const float* base = sub + (size_t)b*64*512 + d;
    float acc = 0.f;
#pragma unroll
    for (int m=0;m<64;m++) acc += base[m*512] * ss[m];
    g_subvec[b*512 + d] = acc;
}

// ---------------- launch -------------------------------------------------------------------
extern "C" void kernel_launch(void* const* d_in, const int* in_sizes, int n_in,
                              void* d_out, int out_size)
{
    const float* x    = (const float*)d_in[0];
    const float* sub  = (const float*)d_in[1];
    const float* W1r  = (const float*)d_in[2];
    const float* b1r  = (const float*)d_in[3];
    const float* W2r  = (const float*)d_in[4];
    const float* W1w  = (const float*)d_in[6];
    const float* b1w  = (const float*)d_in[7];
    const float* W2w  = (const float*)d_in[8];
    const float* Wf   = (const float*)d_in[10];
    const float* bf   = (const float*)d_in[11];
    const float* Wi   = (const float*)d_in[12];
    const float* bi   = (const float*)d_in[13];
    const float* Wc   = (const float*)d_in[14];
    const float* bc   = (const float*)d_in[15];
    const float* Wsub = (const float*)d_in[16];
    const float* bsub = (const float*)d_in[17];
    const float* Wfin = (const float*)d_in[18];
    const float* bfin = (const float*)d_in[19];
    float* out = (float*)d_out;

    cudaFuncSetAttribute(gemm_t, cudaFuncAttributeMaxDynamicSharedMemorySize, SMEM_BYTES);

    prep_k<<<(NC*Dd + 255)/256, 256>>>(W1r, W1w, Wf, Wi, Wc, b1r, b1w, bf, bi, bc);

    // xterm = x @ WX^T + bstack
    gemm_t<<<dim3(NC/BN, Bb/BM), 256, SMEM_BYTES>>>(0, x, nullptr, g_bstack, nullptr, nullptr, nullptr);

    // main: sub_memory @ Wbig^T + xterm -> score partials, F, P
    gemm_t<<<dim3(NC/BN, NROWS/BM), 256, SMEM_BYTES>>>(1, sub, nullptr, nullptr, W2r, W2w, nullptr);

    softmax_k<<<Bb, 64>>>();
    subvec_k<<<Bb, 512>>>(sub);

    // read_vec = tanh(sub_vec @ Wfin^T + bfin) -> out[b,0,:]
    gemm_t<<<dim3(Dd/BN, Bb/BM), 256, SMEM_BYTES>>>(2, nullptr, Wfin, bfin, nullptr, nullptr, out);

    // new_mem = tanh(((1-sw*F)*sub + P*sw) @ Wsub^T + bsub) -> out[b,1+m,:]  (gating fused)
    gemm_t<<<dim3(Dd/BN, NROWS/BM), 256, SMEM_BYTES>>>(3, sub, Wsub, bsub, nullptr, nullptr, out);
}